// round 15
// baseline (speedup 1.0000x reference)
#include <cuda_runtime.h>
#include <cuda_bf16.h>

// Levinson-Durbin, M=24. TWO rows per thread, INTERLEAVED scalar recursions
// (two independent register sets advanced in lockstep -> intra-warp ILP=2).
// out[row] = [K, a0..a23],  R a = -r1,  K = sqrt(E_24).
//
// R14 theory: all shell configs pin issue at 60-65% independent of occupancy
// (38-52%) => the cap is intra-warp ILP in the serial dot chains, phase-
// correlated across warps. Packed f32x2 failed because it kept ILP=1 with
// half the warps; sequential dual-tile kept ILP=1. Interleaving two scalar
// recursions doubles warp eligibility in the low-ILP regions and amortizes
// all per-row overhead (staging addressing, MUFU, control) across 2 rows.

constexpr int M_ORD = 24;
constexpr int NC    = M_ORD + 1;             // 25
constexpr int TPB   = 32;
constexpr int RPB   = 64;                    // 64 rows per warp-CTA (2/thread)
constexpr int TILE_FLOATS = RPB * NC;        // 1600
constexpr int TILE_V4     = TILE_FLOATS / 4; // 400

__device__ __forceinline__ void cp_async16(unsigned saddr, const void* gaddr) {
    asm volatile("cp.async.cg.shared.global [%0], [%1], 16;"
                 :: "r"(saddr), "l"(gaddr));
}
__device__ __forceinline__ void cp_commit() {
    asm volatile("cp.async.commit_group;");
}
template <int N>
__device__ __forceinline__ void cp_wait() {
    asm volatile("cp.async.wait_group %0;" :: "n"(N));
}
// -(1/x): negation folded into the MUFU operand
__device__ __forceinline__ float nrcp(float x) {
    float y; asm("rcp.approx.f32 %0, %1;" : "=f"(y) : "f"(-x)); return y;
}
__device__ __forceinline__ float fsqrt_fast(float x) {
    float y; asm("sqrt.approx.f32 %0, %1;" : "=f"(y) : "f"(x)); return y;
}

__global__ __launch_bounds__(TPB)
void levinson_durbin_kernel(const float* __restrict__ r,
                            float* __restrict__ out,
                            int nrows)
{
    __shared__ float sbuf[TILE_FLOATS];      // 6.4 KB
    const int lane = threadIdx.x;            // TPB == 32
    const int row0 = blockIdx.x * RPB;

    if (row0 + RPB <= nrows) {
        // ---- async prefetch of the 64-row tile (coalesced 16B chunks) ----
        unsigned s = (unsigned)__cvta_generic_to_shared(&sbuf[0]);
        const float4* g = reinterpret_cast<const float4*>(r + (size_t)row0 * NC);
        #pragma unroll
        for (int i = lane; i < TILE_V4; i += TPB) cp_async16(s + i * 16, g + i);
        cp_commit();
        cp_wait<0>();
        __syncwarp();

        // two independent rows per thread: lane and lane+32
        float rrA[NC], rrB[NC];
        #pragma unroll
        for (int i = 0; i < NC; i++) {
            rrA[i] = sbuf[lane * NC + i];
            rrB[i] = sbuf[(lane + 32) * NC + i];
        }

        // ---- interleaved dual Levinson-Durbin recursion ----
        float aA[M_ORD], aB[M_ORD];
        float EA = rrA[0],        EB = rrB[0];
        float nIA = nrcp(EA),     nIB = nrcp(EB);   // -1/E, pipelined

        #pragma unroll
        for (int m = 0; m < M_ORD; m++) {
            // dots: two independent serial chains interleave (ILP=2);
            // 2-way split on each for long m keeps chains <= ~12 FMAs.
            float accA, accB;
            if (m <= 11) {
                float sA = rrA[m + 1], sB = rrB[m + 1];
                #pragma unroll
                for (int i = 0; i < m; i++) {
                    sA = fmaf(aA[i], rrA[m - i], sA);
                    sB = fmaf(aB[i], rrB[m - i], sB);
                }
                accA = sA; accB = sB;
            } else {
                float sA0 = rrA[m + 1], sA1 = 0.0f;
                float sB0 = rrB[m + 1], sB1 = 0.0f;
                #pragma unroll
                for (int i = 0; i + 1 < m; i += 2) {
                    sA0 = fmaf(aA[i    ], rrA[m - i    ], sA0);
                    sB0 = fmaf(aB[i    ], rrB[m - i    ], sB0);
                    sA1 = fmaf(aA[i + 1], rrA[m - i - 1], sA1);
                    sB1 = fmaf(aB[i + 1], rrB[m - i - 1], sB1);
                }
                if (m & 1) {
                    sA0 = fmaf(aA[m - 1], rrA[1], sA0);
                    sB0 = fmaf(aB[m - 1], rrB[1], sB0);
                }
                accA = sA0 + sA1; accB = sB0 + sB1;
            }

            float kA = accA * nIA;           // k = -acc/E (MUFU hidden)
            float kB = accB * nIB;

            // symmetric in-place updates (high ILP, interleaved A/B)
            #pragma unroll
            for (int i = 0; i < m / 2; i++) {
                float tA = aA[i], uA = aA[m - 1 - i];
                float tB = aB[i], uB = aB[m - 1 - i];
                aA[i]         = fmaf(kA, uA, tA);
                aB[i]         = fmaf(kB, uB, tB);
                aA[m - 1 - i] = fmaf(kA, tA, uA);
                aB[m - 1 - i] = fmaf(kB, tB, uB);
            }
            if (m & 1) {
                float tA = aA[m / 2], tB = aB[m / 2];
                aA[m / 2] = fmaf(kA, tA, tA);
                aB[m / 2] = fmaf(kB, tB, tB);
            }
            aA[m] = kA; aB[m] = kB;

            EA  = fmaf(kA, accA, EA);        // E *= (1 - k^2)
            EB  = fmaf(kB, accB, EB);
            nIA = nrcp(EA);                  // hide under next dot
            nIB = nrcp(EB);
        }
        const float KA = fsqrt_fast(EA);
        const float KB = fsqrt_fast(EB);

        // stage outputs into own rows (owner-only writes)
        sbuf[lane * NC + 0]        = KA;
        sbuf[(lane + 32) * NC + 0] = KB;
        #pragma unroll
        for (int i = 0; i < M_ORD; i++) {
            sbuf[lane * NC + 1 + i]        = aA[i];
            sbuf[(lane + 32) * NC + 1 + i] = aB[i];
        }
        __syncwarp();

        // coalesced vector store of the 64-row tile
        float4* o = reinterpret_cast<float4*>(out + (size_t)row0 * NC);
        const float4* sb = reinterpret_cast<const float4*>(&sbuf[0]);
        #pragma unroll
        for (int i = lane; i < TILE_V4; i += TPB) o[i] = sb[i];
    } else {
        // generic tail path (not hit for BATCH=262144)
        #pragma unroll
        for (int t = 0; t < 2; t++) {
            int row = row0 + t * 32 + lane;
            if (row >= nrows) continue;
            float rr[NC], a[M_ORD];
            #pragma unroll
            for (int i = 0; i < NC; i++) rr[i] = r[(size_t)row * NC + i];
            float E = rr[0];
            float ninvE = nrcp(E);
            #pragma unroll
            for (int m = 0; m < M_ORD; m++) {
                float s0 = rr[m + 1], s1 = 0.0f;
                #pragma unroll
                for (int i = 0; i + 1 < m; i += 2) {
                    s0 = fmaf(a[i    ], rr[m - i    ], s0);
                    s1 = fmaf(a[i + 1], rr[m - i - 1], s1);
                }
                if (m & 1) s0 = fmaf(a[m - 1], rr[1], s0);
                float acc = s0 + s1;
                float k = acc * ninvE;
                #pragma unroll
                for (int i = 0; i < m / 2; i++) {
                    float x = a[i], y = a[m - 1 - i];
                    a[i]         = fmaf(k, y, x);
                    a[m - 1 - i] = fmaf(k, x, y);
                }
                if (m & 1) { float x = a[m / 2]; a[m / 2] = fmaf(k, x, x); }
                a[m] = k;
                E = fmaf(k, acc, E);
                ninvE = nrcp(E);
            }
            out[(size_t)row * NC + 0] = fsqrt_fast(E);
            #pragma unroll
            for (int i = 0; i < M_ORD; i++)
                out[(size_t)row * NC + 1 + i] = a[i];
        }
    }
}

extern "C" void kernel_launch(void* const* d_in, const int* in_sizes, int n_in,
                              void* d_out, int out_size)
{
    const float* r = (const float*)d_in[0];
    float* out = (float*)d_out;
    const int nrows = in_sizes[0] / NC;
    const int grid = (nrows + RPB - 1) / RPB;
    levinson_durbin_kernel<<<grid, TPB>>>(r, out, nrows);
}

// round 16
// speedup vs baseline: 1.0021x; 1.0021x over previous
#include <cuda_runtime.h>
#include <cuda_bf16.h>

// Levinson-Durbin, M=24. ONE row per thread; warp-autonomous; each warp
// processes TWO 32-row tiles with both cp.async prefetches issued up front
// (tile-B DRAM latency hides under tile-A compute).
// out[row] = [K, a0..a23],  R a = -r1,  K = sqrt(E_24).
//
// R15 = consolidation of every measured winner:
//  - R8 shell: TPB=64, warp-private tiles/groups, __syncwarp only,
//    __launch_bounds__(64,18) -> 56 regs (best timed config).
//  - R7 pipeline: 2 tiles/warp prefetched at start; A-store overlaps B.
//  - R11 math: serial dot m<=11 (zero join overhead), 2-way split m>=12,
//    pipelined rcp(-E), E += k*acc identity, sqrt.approx.
// One-row-per-thread is the proven register-stable basin (packed f32x2,
// sequential-dual, and interleaved-dual all lost to pressure/ILP effects).

constexpr int M_ORD = 24;
constexpr int NC    = M_ORD + 1;               // 25
constexpr int TPB   = 64;
constexpr int WARPS = TPB / 32;                // 2
constexpr int ROWS_PER_WARP_TILE = 32;
constexpr int TILES_PER_WARP = 2;
constexpr int RPB = TPB * TILES_PER_WARP;      // 128 rows per CTA
constexpr int WTILE_FLOATS = ROWS_PER_WARP_TILE * NC;  // 800
constexpr int WTILE_V4     = WTILE_FLOATS / 4;         // 200

__device__ __forceinline__ void cp_async16(unsigned saddr, const void* gaddr) {
    asm volatile("cp.async.cg.shared.global [%0], [%1], 16;"
                 :: "r"(saddr), "l"(gaddr));
}
__device__ __forceinline__ void cp_commit() {
    asm volatile("cp.async.commit_group;");
}
template <int N>
__device__ __forceinline__ void cp_wait() {
    asm volatile("cp.async.wait_group %0;" :: "n"(N));
}
// -(1/x): negation folded into the MUFU operand
__device__ __forceinline__ float nrcp(float x) {
    float y; asm("rcp.approx.f32 %0, %1;" : "=f"(y) : "f"(-x)); return y;
}
__device__ __forceinline__ float fsqrt_fast(float x) {
    float y; asm("sqrt.approx.f32 %0, %1;" : "=f"(y) : "f"(x)); return y;
}

// Full Levinson-Durbin recursion; returns K = sqrt(E_M), fills a[0..23].
// Minimal fma-pipe op count: serial dot m<=11, 2-way split m>=12.
__device__ __forceinline__ float levdur(const float rr[NC], float a[M_ORD]) {
    float E     = rr[0];
    float ninvE = nrcp(E);                     // -1/E, pipelined one iter ahead
    #pragma unroll
    for (int m = 0; m < M_ORD; m++) {
        float acc;
        if (m <= 11) {
            float s0 = rr[m + 1];
            #pragma unroll
            for (int i = 0; i < m; i++) s0 = fmaf(a[i], rr[m - i], s0);
            acc = s0;
        } else {
            float s0 = rr[m + 1], s1 = 0.0f;
            #pragma unroll
            for (int i = 0; i + 1 < m; i += 2) {
                s0 = fmaf(a[i    ], rr[m - i    ], s0);
                s1 = fmaf(a[i + 1], rr[m - i - 1], s1);
            }
            if (m & 1) s0 = fmaf(a[m - 1], rr[1], s0);
            acc = s0 + s1;
        }

        float k = acc * ninvE;                 // k = -acc/E (MUFU hidden)

        // symmetric in-place update: a_i' = a_i + k * a_{m-1-i}
        #pragma unroll
        for (int i = 0; i < m / 2; i++) {
            float t = a[i];
            float u = a[m - 1 - i];
            a[i]         = fmaf(k, u, t);
            a[m - 1 - i] = fmaf(k, t, u);
        }
        if (m & 1) {
            float t = a[m / 2];
            a[m / 2] = fmaf(k, t, t);
        }
        a[m] = k;

        E     = fmaf(k, acc, E);               // E *= (1 - k^2)
        ninvE = nrcp(E);                       // hides under next dot
    }
    return fsqrt_fast(E);
}

__global__ __launch_bounds__(TPB, 18)          // caps regs at 56 (R8 optimum)
void levinson_durbin_kernel(const float* __restrict__ r,
                            float* __restrict__ out,
                            int nrows)
{
    // [warp][tile][data]: each warp owns 2 private 3.2KB tiles
    __shared__ float sbuf[WARPS][TILES_PER_WARP][WTILE_FLOATS];  // 12.8 KB
    const int lane = threadIdx.x & 31;
    const int wid  = threadIdx.x >> 5;
    // warp's first tile start row; its second tile is +32 rows
    const int wrow0 = blockIdx.x * RPB + wid * (TILES_PER_WARP * ROWS_PER_WARP_TILE);

    float rr[NC];
    float a[M_ORD];

    if (wrow0 + TILES_PER_WARP * ROWS_PER_WARP_TILE <= nrows) {
        // ---- prefetch BOTH tiles (separate per-warp commit groups) ----
        unsigned s0 = (unsigned)__cvta_generic_to_shared(&sbuf[wid][0][0]);
        unsigned s1 = (unsigned)__cvta_generic_to_shared(&sbuf[wid][1][0]);
        const float4* g0 = reinterpret_cast<const float4*>(r + (size_t)wrow0 * NC);
        const float4* g1 = reinterpret_cast<const float4*>(
            r + (size_t)(wrow0 + ROWS_PER_WARP_TILE) * NC);
        #pragma unroll
        for (int i = lane; i < WTILE_V4; i += 32) cp_async16(s0 + i * 16, g0 + i);
        cp_commit();
        #pragma unroll
        for (int i = lane; i < WTILE_V4; i += 32) cp_async16(s1 + i * 16, g1 + i);
        cp_commit();

        // ---- tile A (tile B copy still in flight) ----
        cp_wait<1>();
        __syncwarp();
        #pragma unroll
        for (int i = 0; i < NC; i++) rr[i] = sbuf[wid][0][lane * NC + i];

        float Kv = levdur(rr, a);

        // stage output A into the consumed buffer (owner-only rows)
        sbuf[wid][0][lane * NC + 0] = Kv;
        #pragma unroll
        for (int i = 0; i < M_ORD; i++) sbuf[wid][0][lane * NC + 1 + i] = a[i];
        __syncwarp();

        // coalesced store of tile A (overlaps tile-B availability)
        float4* o0 = reinterpret_cast<float4*>(out + (size_t)wrow0 * NC);
        const float4* sb0 = reinterpret_cast<const float4*>(&sbuf[wid][0][0]);
        #pragma unroll
        for (int i = lane; i < WTILE_V4; i += 32) o0[i] = sb0[i];

        // ---- tile B ----
        cp_wait<0>();
        __syncwarp();
        #pragma unroll
        for (int i = 0; i < NC; i++) rr[i] = sbuf[wid][1][lane * NC + i];

        Kv = levdur(rr, a);

        sbuf[wid][1][lane * NC + 0] = Kv;
        #pragma unroll
        for (int i = 0; i < M_ORD; i++) sbuf[wid][1][lane * NC + 1 + i] = a[i];
        __syncwarp();

        float4* o1 = reinterpret_cast<float4*>(
            out + (size_t)(wrow0 + ROWS_PER_WARP_TILE) * NC);
        const float4* sb1 = reinterpret_cast<const float4*>(&sbuf[wid][1][0]);
        #pragma unroll
        for (int i = lane; i < WTILE_V4; i += 32) o1[i] = sb1[i];
    } else {
        // generic tail path (not hit for BATCH=262144)
        #pragma unroll
        for (int t = 0; t < TILES_PER_WARP; t++) {
            int row = wrow0 + t * ROWS_PER_WARP_TILE + lane;
            if (row >= nrows) continue;
            #pragma unroll
            for (int i = 0; i < NC; i++) rr[i] = r[(size_t)row * NC + i];
            float Kv = levdur(rr, a);
            out[(size_t)row * NC + 0] = Kv;
            #pragma unroll
            for (int i = 0; i < M_ORD; i++)
                out[(size_t)row * NC + 1 + i] = a[i];
        }
    }
}

extern "C" void kernel_launch(void* const* d_in, const int* in_sizes, int n_in,
                              void* d_out, int out_size)
{
    const float* r = (const float*)d_in[0];
    float* out = (float*)d_out;
    const int nrows = in_sizes[0] / NC;
    const int grid = (nrows + RPB - 1) / RPB;
    levinson_durbin_kernel<<<grid, TPB>>>(r, out, nrows);
}